// round 3
// baseline (speedup 1.0000x reference)
#include <cuda_runtime.h>
#include <cstdint>

#define D 128
#define P 8
#define NMAX 100000
#define LMAX 3
#define ROWS_BLK 64
#define AS_STRIDE 132   // A smem row stride: frag banks 4g+t all distinct
#define BS_STRIDE 136   // B smem row stride: frag banks 8t+g all distinct

// Scratch (device globals — no allocation allowed)
__device__ float g_hA[(size_t)NMAX * D];
__device__ float g_hB[(size_t)NMAX * D];
__device__ int   g_row_ptr[NMAX + 1];
__device__ float g_wwT[LMAX * D * D];   // [l][k][o]

// ---------------------------------------------------------------------------
__global__ void build_row_ptr_k(const int* __restrict__ edge_row, int E, int N) {
    int r = blockIdx.x * blockDim.x + threadIdx.x;
    if (r > N) return;
    int lo = 0, hi = E;
    while (lo < hi) {
        int mid = (lo + hi) >> 1;
        if (edge_row[mid] < r) lo = mid + 1; else hi = mid;
    }
    g_row_ptr[r] = lo;
}

// ---------------------------------------------------------------------------
__global__ void build_weights_k(const float* __restrict__ sp, const float* __restrict__ lw) {
    int l = blockIdx.x >> 7;
    int i = blockIdx.x & 127;
    int o = threadIdx.x;

    float w[P];
    float m = -1e30f;
#pragma unroll
    for (int p = 0; p < P; p++) { w[p] = lw[l * P + p]; m = fmaxf(m, w[p]); }
    float s = 0.f;
#pragma unroll
    for (int p = 0; p < P; p++) { w[p] = expf(w[p] - m); s += w[p]; }
    float inv = 1.f / s;

    const float* base = sp + (((size_t)l * D + o) * D + i) * P;
    float acc = 0.f;
#pragma unroll
    for (int p = 0; p < P; p++) acc = fmaf(base[p], w[p] * inv, acc);
    g_wwT[((size_t)l * D + i) * D + o] = acc;
}

// ---------------------------------------------------------------------------
__device__ __forceinline__ void mma_tf32(float (&d)[4],
                                         uint32_t a0, uint32_t a1, uint32_t a2, uint32_t a3,
                                         uint32_t b0, uint32_t b1) {
    asm volatile(
        "mma.sync.aligned.m16n8k8.row.col.f32.tf32.tf32.f32 "
        "{%0,%1,%2,%3},{%4,%5,%6,%7},{%8,%9},{%0,%1,%2,%3};"
        : "+f"(d[0]), "+f"(d[1]), "+f"(d[2]), "+f"(d[3])
        : "r"(a0), "r"(a1), "r"(a2), "r"(a3), "r"(b0), "r"(b1));
}

__device__ __forceinline__ void split_tf32(float v, uint32_t& hi, uint32_t& lo) {
    uint32_t h = __float_as_uint(v) & 0xffffe000u;
    hi = h;
    lo = __float_as_uint(v - __uint_as_float(h));
}

// ---------------------------------------------------------------------------
// Fused layer: block = 64 rows. Phase 1: gather SpMM tile into smem.
// Phase 2: 3xTF32 MMA tile x B -> C (with optional ReLU).
// 2 blocks/SM -> gather (L2-bound) of one block overlaps MMA (tensor-bound)
// of the other.
// ---------------------------------------------------------------------------
template <bool RELU>
__global__ __launch_bounds__(256) void fused_layer_k(
    const int* __restrict__ col, const float* __restrict__ val,
    const float* __restrict__ h, const float* __restrict__ Bm,
    float* __restrict__ C, int N)
{
    extern __shared__ float smem[];
    float* As = smem;                        // [64][AS_STRIDE]
    float* Bs = smem + ROWS_BLK * AS_STRIDE; // [128][BS_STRIDE]

    const int tid  = threadIdx.x;
    const int warp = tid >> 5;
    const int lane = tid & 31;

    // ---- stage B (128x128) ----
#pragma unroll
    for (int i = tid; i < 128 * 32; i += 256) {
        int row = i >> 5;
        int c4  = (i & 31) << 2;
        float4 v = __ldg((const float4*)(Bm + row * 128 + c4));
        *(float4*)&Bs[row * BS_STRIDE + c4] = v;
    }

    // ---- phase 1: gather 64 rows into As ----
    const int base = blockIdx.x * ROWS_BLK;
#pragma unroll
    for (int i = 0; i < 8; i++) {
        int lr = warp * 8 + i;
        int r  = base + lr;
        float4 acc0 = make_float4(0.f, 0.f, 0.f, 0.f);
        float4 acc1 = make_float4(0.f, 0.f, 0.f, 0.f);
        if (r < N) {
            int s = g_row_ptr[r];
            int e = g_row_ptr[r + 1];
            int k = s;
            for (; k + 1 < e; k += 2) {
                int   c0 = __ldg(col + k);
                int   c1 = __ldg(col + k + 1);
                float v0 = __ldg(val + k);
                float v1 = __ldg(val + k + 1);
                float4 h0 = __ldg(((const float4*)(h + (size_t)c0 * D)) + lane);
                float4 h1 = __ldg(((const float4*)(h + (size_t)c1 * D)) + lane);
                acc0.x = fmaf(v0, h0.x, acc0.x); acc0.y = fmaf(v0, h0.y, acc0.y);
                acc0.z = fmaf(v0, h0.z, acc0.z); acc0.w = fmaf(v0, h0.w, acc0.w);
                acc1.x = fmaf(v1, h1.x, acc1.x); acc1.y = fmaf(v1, h1.y, acc1.y);
                acc1.z = fmaf(v1, h1.z, acc1.z); acc1.w = fmaf(v1, h1.w, acc1.w);
            }
            if (k < e) {
                int   c0 = __ldg(col + k);
                float v0 = __ldg(val + k);
                float4 h0 = __ldg(((const float4*)(h + (size_t)c0 * D)) + lane);
                acc0.x = fmaf(v0, h0.x, acc0.x); acc0.y = fmaf(v0, h0.y, acc0.y);
                acc0.z = fmaf(v0, h0.z, acc0.z); acc0.w = fmaf(v0, h0.w, acc0.w);
            }
        }
        acc0.x += acc1.x; acc0.y += acc1.y; acc0.z += acc1.z; acc0.w += acc1.w;
        *(float4*)&As[lr * AS_STRIDE + lane * 4] = acc0;
    }
    __syncthreads();

    // ---- phase 2: MMA. warp tile = 16 rows x 64 cols ----
    const int g  = lane >> 2;
    const int t  = lane & 3;
    const int wr = warp >> 1;        // 0..3  (row group of 16)
    const int wc = warp & 1;         // 0..1  (col group of 64)

    float acc[8][4];
#pragma unroll
    for (int j = 0; j < 8; j++)
#pragma unroll
        for (int q = 0; q < 4; q++) acc[j][q] = 0.f;

    const float* arow0 = &As[(wr * 16 + g) * AS_STRIDE];
    const float* arow1 = &As[(wr * 16 + g + 8) * AS_STRIDE];

#pragma unroll
    for (int kk = 0; kk < 128; kk += 8) {
        float a0f = arow0[kk + t];
        float a1f = arow1[kk + t];
        float a2f = arow0[kk + t + 4];
        float a3f = arow1[kk + t + 4];

        uint32_t a0h, a0l, a1h, a1l, a2h, a2l, a3h, a3l;
        split_tf32(a0f, a0h, a0l);
        split_tf32(a1f, a1h, a1l);
        split_tf32(a2f, a2h, a2l);
        split_tf32(a3f, a3h, a3l);

        const float* b0p = &Bs[(kk + t) * BS_STRIDE + wc * 64 + g];
        const float* b1p = &Bs[(kk + t + 4) * BS_STRIDE + wc * 64 + g];

#pragma unroll
        for (int j = 0; j < 8; j++) {
            float b0f = b0p[j * 8];
            float b1f = b1p[j * 8];
            uint32_t b0h, b0l, b1h, b1l;
            split_tf32(b0f, b0h, b0l);
            split_tf32(b1f, b1h, b1l);
            mma_tf32(acc[j], a0l, a1l, a2l, a3l, b0h, b1h);
            mma_tf32(acc[j], a0h, a1h, a2h, a3h, b0l, b1l);
            mma_tf32(acc[j], a0h, a1h, a2h, a3h, b0h, b1h);
        }
    }

    // ---- epilogue ----
    const int rA = base + wr * 16 + g;
    const int rB = rA + 8;
#pragma unroll
    for (int j = 0; j < 8; j++) {
        float v0 = acc[j][0], v1 = acc[j][1], v2 = acc[j][2], v3 = acc[j][3];
        if (RELU) {
            v0 = fmaxf(v0, 0.f); v1 = fmaxf(v1, 0.f);
            v2 = fmaxf(v2, 0.f); v3 = fmaxf(v3, 0.f);
        }
        int c = wc * 64 + j * 8 + 2 * t;
        if (rA < N) *(float2*)(C + (size_t)rA * D + c) = make_float2(v0, v1);
        if (rB < N) *(float2*)(C + (size_t)rB * D + c) = make_float2(v2, v3);
    }
}

// ---------------------------------------------------------------------------
extern "C" void kernel_launch(void* const* d_in, const int* in_sizes, int n_in,
                              void* d_out, int out_size) {
    const int*   edge_row  = (const int*)d_in[0];
    const int*   edge_col  = (const int*)d_in[1];
    const float* edge_vals = (const float*)d_in[2];
    const float* x         = (const float*)d_in[3];
    const float* sp        = (const float*)d_in[4];
    const float* lw        = (const float*)d_in[5];
    float*       out       = (float*)d_out;

    const int E = in_sizes[0];
    const int N = in_sizes[3] / D;
    const int L = in_sizes[5] / P;

    void *p_hA, *p_hB, *p_ww;
    cudaGetSymbolAddress(&p_hA, g_hA);
    cudaGetSymbolAddress(&p_hB, g_hB);
    cudaGetSymbolAddress(&p_ww, g_wwT);

    const int smem_bytes = (ROWS_BLK * AS_STRIDE + 128 * BS_STRIDE) * 4; // 103424
    cudaFuncSetAttribute(fused_layer_k<true>,  cudaFuncAttributeMaxDynamicSharedMemorySize, smem_bytes);
    cudaFuncSetAttribute(fused_layer_k<false>, cudaFuncAttributeMaxDynamicSharedMemorySize, smem_bytes);

    build_row_ptr_k<<<(N + 256) / 256, 256>>>(edge_row, E, N);
    build_weights_k<<<L * D, D>>>(sp, lw);

    float* bufs[2] = {(float*)p_hA, (float*)p_hB};
    const float* hin = x;
    const int blocks = (N + ROWS_BLK - 1) / ROWS_BLK;

    for (int l = 0; l < L; l++) {
        const float* Bm = (const float*)p_ww + (size_t)l * D * D;
        float* Cout = (l == L - 1) ? out : bufs[l & 1];
        if (l < L - 1)
            fused_layer_k<true><<<blocks, 256, smem_bytes>>>(edge_col, edge_vals, hin, Bm, Cout, N);
        else
            fused_layer_k<false><<<blocks, 256, smem_bytes>>>(edge_col, edge_vals, hin, Bm, Cout, N);
        hin = Cout;
    }
}

// round 4
// speedup vs baseline: 1.7201x; 1.7201x over previous
#include <cuda_runtime.h>
#include <cstdint>

#define D 128
#define P 8
#define NMAX 100000
#define LMAX 3
#define BS_STRIDE 72    // Bs stride: frag bank = (8t + 8j + g) % 32, all 32 distinct

// Scratch (device globals — no allocation allowed)
__device__ float g_ax[(size_t)NMAX * D];
__device__ float g_hA[(size_t)NMAX * D];
__device__ float g_hB[(size_t)NMAX * D];
__device__ int   g_row_ptr[NMAX + 1];
__device__ float g_wwT[LMAX * D * D];   // [l][k][o]

// ---------------------------------------------------------------------------
__global__ void build_row_ptr_k(const int* __restrict__ edge_row, int E, int N) {
    int r = blockIdx.x * blockDim.x + threadIdx.x;
    if (r > N) return;
    int lo = 0, hi = E;
    while (lo < hi) {
        int mid = (lo + hi) >> 1;
        if (edge_row[mid] < r) lo = mid + 1; else hi = mid;
    }
    g_row_ptr[r] = lo;
}

// ---------------------------------------------------------------------------
__global__ void build_weights_k(const float* __restrict__ sp, const float* __restrict__ lw) {
    int l = blockIdx.x >> 7;
    int i = blockIdx.x & 127;
    int o = threadIdx.x;

    float w[P];
    float m = -1e30f;
#pragma unroll
    for (int p = 0; p < P; p++) { w[p] = lw[l * P + p]; m = fmaxf(m, w[p]); }
    float s = 0.f;
#pragma unroll
    for (int p = 0; p < P; p++) { w[p] = expf(w[p] - m); s += w[p]; }
    float inv = 1.f / s;

    const float* base = sp + (((size_t)l * D + o) * D + i) * P;
    float acc = 0.f;
#pragma unroll
    for (int p = 0; p < P; p++) acc = fmaf(base[p], w[p] * inv, acc);
    g_wwT[((size_t)l * D + i) * D + o] = acc;
}

// ---------------------------------------------------------------------------
// SpMM: one warp per row, 2-edge unroll for MLP. (At L2-gather floor.)
// ---------------------------------------------------------------------------
__global__ void spmm_k(const int* __restrict__ col, const float* __restrict__ val,
                       const float* __restrict__ h, int N) {
    int warp = (int)((blockIdx.x * blockDim.x + threadIdx.x) >> 5);
    int lane = threadIdx.x & 31;
    if (warp >= N) return;
    int s = g_row_ptr[warp];
    int e = g_row_ptr[warp + 1];
    float4 acc0 = make_float4(0.f, 0.f, 0.f, 0.f);
    float4 acc1 = make_float4(0.f, 0.f, 0.f, 0.f);
    int k = s;
    for (; k + 1 < e; k += 2) {
        int   c0 = __ldg(col + k);
        int   c1 = __ldg(col + k + 1);
        float v0 = __ldg(val + k);
        float v1 = __ldg(val + k + 1);
        float4 h0 = __ldg(((const float4*)(h + (size_t)c0 * D)) + lane);
        float4 h1 = __ldg(((const float4*)(h + (size_t)c1 * D)) + lane);
        acc0.x = fmaf(v0, h0.x, acc0.x); acc0.y = fmaf(v0, h0.y, acc0.y);
        acc0.z = fmaf(v0, h0.z, acc0.z); acc0.w = fmaf(v0, h0.w, acc0.w);
        acc1.x = fmaf(v1, h1.x, acc1.x); acc1.y = fmaf(v1, h1.y, acc1.y);
        acc1.z = fmaf(v1, h1.z, acc1.z); acc1.w = fmaf(v1, h1.w, acc1.w);
    }
    if (k < e) {
        int   c0 = __ldg(col + k);
        float v0 = __ldg(val + k);
        float4 h0 = __ldg(((const float4*)(h + (size_t)c0 * D)) + lane);
        acc0.x = fmaf(v0, h0.x, acc0.x); acc0.y = fmaf(v0, h0.y, acc0.y);
        acc0.z = fmaf(v0, h0.z, acc0.z); acc0.w = fmaf(v0, h0.w, acc0.w);
    }
    acc0.x += acc1.x; acc0.y += acc1.y; acc0.z += acc1.z; acc0.w += acc1.w;
    ((float4*)(g_ax + (size_t)warp * D))[lane] = acc0;
}

// ---------------------------------------------------------------------------
__device__ __forceinline__ void mma_tf32(float (&d)[4],
                                         uint32_t a0, uint32_t a1, uint32_t a2, uint32_t a3,
                                         uint32_t b0, uint32_t b1) {
    asm volatile(
        "mma.sync.aligned.m16n8k8.row.col.f32.tf32.tf32.f32 "
        "{%0,%1,%2,%3},{%4,%5,%6,%7},{%8,%9},{%0,%1,%2,%3};"
        : "+f"(d[0]), "+f"(d[1]), "+f"(d[2]), "+f"(d[3])
        : "r"(a0), "r"(a1), "r"(a2), "r"(a3), "r"(b0), "r"(b1));
}

__device__ __forceinline__ void split_tf32(float v, uint32_t& hi, uint32_t& lo) {
    uint32_t h = __float_as_uint(v) & 0xffffe000u;
    hi = h;
    lo = __float_as_uint(v - __uint_as_float(h));
}

// ---------------------------------------------------------------------------
// Tensor-core GEMM (3xTF32): block = 128 rows x 64 cols. B hi/lo pre-split
// into smem at staging; inner loop is pure LDS + MMA. 3 blocks/SM.
// ---------------------------------------------------------------------------
template <bool RELU>
__global__ __launch_bounds__(256, 3) void gemm_tc(const float* __restrict__ A,
                                                  const float* __restrict__ B,
                                                  float* __restrict__ C, int N) {
    extern __shared__ float smem[];
    float* BsH = smem;                    // [128][BS_STRIDE]
    float* BsL = smem + 128 * BS_STRIDE;  // [128][BS_STRIDE]

    const int tid     = threadIdx.x;
    const int col_off = (blockIdx.x & 1) << 6;   // 0 or 64

    // stage B slice (128 x 64), split hi/lo once
#pragma unroll
    for (int i = tid; i < 128 * 16; i += 256) {
        int row = i >> 4;
        int c4  = (i & 15) << 2;
        float4 v = __ldg((const float4*)(B + row * 128 + col_off + c4));
        float* dh = &BsH[row * BS_STRIDE + c4];
        float* dl = &BsL[row * BS_STRIDE + c4];
        uint32_t h0, l0, h1, l1, h2, l2, h3, l3;
        split_tf32(v.x, h0, l0); split_tf32(v.y, h1, l1);
        split_tf32(v.z, h2, l2); split_tf32(v.w, h3, l3);
        dh[0] = __uint_as_float(h0); dh[1] = __uint_as_float(h1);
        dh[2] = __uint_as_float(h2); dh[3] = __uint_as_float(h3);
        dl[0] = __uint_as_float(l0); dl[1] = __uint_as_float(l1);
        dl[2] = __uint_as_float(l2); dl[3] = __uint_as_float(l3);
    }
    __syncthreads();

    const int warp = tid >> 5;
    const int lane = tid & 31;
    const int g = lane >> 2;
    const int t = lane & 3;

    const int row0 = (blockIdx.x >> 1) * 128 + warp * 16;
    const int rA = row0 + g;
    const int rB = row0 + g + 8;
    const bool okA = rA < N;
    const bool okB = rB < N;

    const float* pA  = A + (size_t)rA * D;
    const float* pA2 = A + (size_t)rB * D;

    float acc[8][4];
#pragma unroll
    for (int j = 0; j < 8; j++)
#pragma unroll
        for (int q = 0; q < 4; q++) acc[j][q] = 0.f;

#pragma unroll
    for (int kk = 0; kk < 128; kk += 8) {
        float a0f = okA ? __ldg(pA  + kk + t)     : 0.f;
        float a2f = okA ? __ldg(pA  + kk + t + 4) : 0.f;
        float a1f = okB ? __ldg(pA2 + kk + t)     : 0.f;
        float a3f = okB ? __ldg(pA2 + kk + t + 4) : 0.f;

        uint32_t a0h, a0l, a1h, a1l, a2h, a2l, a3h, a3l;
        split_tf32(a0f, a0h, a0l);
        split_tf32(a1f, a1h, a1l);
        split_tf32(a2f, a2h, a2l);
        split_tf32(a3f, a3h, a3l);

        const float* bh0 = &BsH[(kk + t) * BS_STRIDE + g];
        const float* bh1 = &BsH[(kk + t + 4) * BS_STRIDE + g];
        const float* bl0 = &BsL[(kk + t) * BS_STRIDE + g];
        const float* bl1 = &BsL[(kk + t + 4) * BS_STRIDE + g];

#pragma unroll
        for (int j = 0; j < 8; j++) {
            uint32_t b0h = __float_as_uint(bh0[j * 8]);
            uint32_t b1h = __float_as_uint(bh1[j * 8]);
            uint32_t b0l = __float_as_uint(bl0[j * 8]);
            uint32_t b1l = __float_as_uint(bl1[j * 8]);
            mma_tf32(acc[j], a0l, a1l, a2l, a3l, b0h, b1h);
            mma_tf32(acc[j], a0h, a1h, a2h, a3h, b0l, b1l);
            mma_tf32(acc[j], a0h, a1h, a2h, a3h, b0h, b1h);
        }
    }

    // epilogue
#pragma unroll
    for (int j = 0; j < 8; j++) {
        float v0 = acc[j][0], v1 = acc[j][1], v2 = acc[j][2], v3 = acc[j][3];
        if (RELU) {
            v0 = fmaxf(v0, 0.f); v1 = fmaxf(v1, 0.f);
            v2 = fmaxf(v2, 0.f); v3 = fmaxf(v3, 0.f);
        }
        int c = col_off + j * 8 + 2 * t;
        if (okA) *(float2*)(C + (size_t)rA * D + c) = make_float2(v0, v1);
        if (okB) *(float2*)(C + (size_t)rB * D + c) = make_float2(v2, v3);
    }
}

// ---------------------------------------------------------------------------
extern "C" void kernel_launch(void* const* d_in, const int* in_sizes, int n_in,
                              void* d_out, int out_size) {
    const int*   edge_row  = (const int*)d_in[0];
    const int*   edge_col  = (const int*)d_in[1];
    const float* edge_vals = (const float*)d_in[2];
    const float* x         = (const float*)d_in[3];
    const float* sp        = (const float*)d_in[4];
    const float* lw        = (const float*)d_in[5];
    float*       out       = (float*)d_out;

    const int E = in_sizes[0];
    const int N = in_sizes[3] / D;
    const int L = in_sizes[5] / P;

    void *p_ax, *p_hA, *p_hB, *p_ww;
    cudaGetSymbolAddress(&p_ax, g_ax);
    cudaGetSymbolAddress(&p_hA, g_hA);
    cudaGetSymbolAddress(&p_hB, g_hB);
    cudaGetSymbolAddress(&p_ww, g_wwT);

    const int smem_bytes = 2 * 128 * BS_STRIDE * 4;   // 73728
    cudaFuncSetAttribute(gemm_tc<true>,  cudaFuncAttributeMaxDynamicSharedMemorySize, smem_bytes);
    cudaFuncSetAttribute(gemm_tc<false>, cudaFuncAttributeMaxDynamicSharedMemorySize, smem_bytes);

    build_row_ptr_k<<<(N + 256) / 256, 256>>>(edge_row, E, N);
    build_weights_k<<<L * D, D>>>(sp, lw);

    float* bufs[2] = {(float*)p_hA, (float*)p_hB};
    const float* hin = x;
    const int gemm_blocks = 2 * ((N + 127) / 128);
    const int spmm_blocks = (N + 7) / 8;

    for (int l = 0; l < L; l++) {
        spmm_k<<<spmm_blocks, 256>>>(edge_col, edge_vals, hin, N);
        const float* Bm = (const float*)p_ww + (size_t)l * D * D;
        float* Cout = (l == L - 1) ? out : bufs[l & 1];
        if (l < L - 1)
            gemm_tc<true><<<gemm_blocks, 256, smem_bytes>>>((const float*)p_ax, Bm, Cout, N);
        else
            gemm_tc<false><<<gemm_blocks, 256, smem_bytes>>>((const float*)p_ax, Bm, Cout, N);
        hin = Cout;
    }
}

// round 5
// speedup vs baseline: 1.8724x; 1.0885x over previous
#include <cuda_runtime.h>
#include <cstdint>

#define D 128
#define P 8
#define NMAX 100000
#define LMAX 3
#define BS_STRIDE 72    // Bs stride: frag bank = (8t + 8j + g) % 32, all 32 distinct

// Scratch (device globals — no allocation allowed)
__device__ float g_ax[(size_t)NMAX * D];
__device__ float g_hA[(size_t)NMAX * D];
__device__ float g_hB[(size_t)NMAX * D];
__device__ int   g_row_ptr[NMAX + 1];
__device__ float g_wwT[LMAX * D * D];   // [l][k][o]

// ---------------------------------------------------------------------------
__global__ void build_row_ptr_k(const int* __restrict__ edge_row, int E, int N) {
    int r = blockIdx.x * blockDim.x + threadIdx.x;
    if (r > N) return;
    int lo = 0, hi = E;
    while (lo < hi) {
        int mid = (lo + hi) >> 1;
        if (edge_row[mid] < r) lo = mid + 1; else hi = mid;
    }
    g_row_ptr[r] = lo;
}

// ---------------------------------------------------------------------------
__global__ void build_weights_k(const float* __restrict__ sp, const float* __restrict__ lw) {
    int l = blockIdx.x >> 7;
    int i = blockIdx.x & 127;
    int o = threadIdx.x;

    float w[P];
    float m = -1e30f;
#pragma unroll
    for (int p = 0; p < P; p++) { w[p] = lw[l * P + p]; m = fmaxf(m, w[p]); }
    float s = 0.f;
#pragma unroll
    for (int p = 0; p < P; p++) { w[p] = expf(w[p] - m); s += w[p]; }
    float inv = 1.f / s;

    const float* base = sp + (((size_t)l * D + o) * D + i) * P;
    float acc = 0.f;
#pragma unroll
    for (int p = 0; p < P; p++) acc = fmaf(base[p], w[p] * inv, acc);
    g_wwT[((size_t)l * D + i) * D + o] = acc;
}

// ---------------------------------------------------------------------------
// SpMM: one warp per row, 2-edge unroll. (At L2-gather floor.)
// ---------------------------------------------------------------------------
__global__ void spmm_k(const int* __restrict__ col, const float* __restrict__ val,
                       const float* __restrict__ h, int N) {
    int warp = (int)((blockIdx.x * blockDim.x + threadIdx.x) >> 5);
    int lane = threadIdx.x & 31;
    if (warp >= N) return;
    int s = g_row_ptr[warp];
    int e = g_row_ptr[warp + 1];
    float4 acc0 = make_float4(0.f, 0.f, 0.f, 0.f);
    float4 acc1 = make_float4(0.f, 0.f, 0.f, 0.f);
    int k = s;
    for (; k + 1 < e; k += 2) {
        int   c0 = __ldg(col + k);
        int   c1 = __ldg(col + k + 1);
        float v0 = __ldg(val + k);
        float v1 = __ldg(val + k + 1);
        float4 h0 = __ldg(((const float4*)(h + (size_t)c0 * D)) + lane);
        float4 h1 = __ldg(((const float4*)(h + (size_t)c1 * D)) + lane);
        acc0.x = fmaf(v0, h0.x, acc0.x); acc0.y = fmaf(v0, h0.y, acc0.y);
        acc0.z = fmaf(v0, h0.z, acc0.z); acc0.w = fmaf(v0, h0.w, acc0.w);
        acc1.x = fmaf(v1, h1.x, acc1.x); acc1.y = fmaf(v1, h1.y, acc1.y);
        acc1.z = fmaf(v1, h1.z, acc1.z); acc1.w = fmaf(v1, h1.w, acc1.w);
    }
    if (k < e) {
        int   c0 = __ldg(col + k);
        float v0 = __ldg(val + k);
        float4 h0 = __ldg(((const float4*)(h + (size_t)c0 * D)) + lane);
        acc0.x = fmaf(v0, h0.x, acc0.x); acc0.y = fmaf(v0, h0.y, acc0.y);
        acc0.z = fmaf(v0, h0.z, acc0.z); acc0.w = fmaf(v0, h0.w, acc0.w);
    }
    acc0.x += acc1.x; acc0.y += acc1.y; acc0.z += acc1.z; acc0.w += acc1.w;
    ((float4*)(g_ax + (size_t)warp * D))[lane] = acc0;
}

// ---------------------------------------------------------------------------
__device__ __forceinline__ void mma_tf32(float (&d)[4],
                                         uint32_t a0, uint32_t a1, uint32_t a2, uint32_t a3,
                                         uint32_t b0, uint32_t b1) {
    asm volatile(
        "mma.sync.aligned.m16n8k8.row.col.f32.tf32.tf32.f32 "
        "{%0,%1,%2,%3},{%4,%5,%6,%7},{%8,%9},{%0,%1,%2,%3};"
        : "+f"(d[0]), "+f"(d[1]), "+f"(d[2]), "+f"(d[3])
        : "r"(a0), "r"(a1), "r"(a2), "r"(a3), "r"(b0), "r"(b1));
}

__device__ __forceinline__ void split_tf32(float v, uint32_t& hi, uint32_t& lo) {
    uint32_t h = __float_as_uint(v) & 0xffffe000u;
    hi = h;
    lo = __float_as_uint(v - __uint_as_float(h));
}

// ---------------------------------------------------------------------------
// Tensor-core GEMM (3xTF32): block = 256 rows x 64 cols, 8 warps.
// Warp M-tile = 32 rows (2 mma row-sets) -> each B fragment feeds 6 MMAs.
// B hi/lo pre-split in smem; inner loop = pure LDS + MMA.
// ---------------------------------------------------------------------------
template <bool RELU>
__global__ __launch_bounds__(256, 2) void gemm_tc(const float* __restrict__ A,
                                                  const float* __restrict__ B,
                                                  float* __restrict__ C, int N) {
    extern __shared__ float smem[];
    float* BsH = smem;                    // [128][BS_STRIDE]
    float* BsL = smem + 128 * BS_STRIDE;  // [128][BS_STRIDE]

    const int tid     = threadIdx.x;
    const int col_off = (blockIdx.x & 1) << 6;   // 0 or 64

    // stage B slice (128 x 64), split hi/lo once
#pragma unroll
    for (int i = tid; i < 128 * 16; i += 256) {
        int row = i >> 4;
        int c4  = (i & 15) << 2;
        float4 v = __ldg((const float4*)(B + row * 128 + col_off + c4));
        float* dh = &BsH[row * BS_STRIDE + c4];
        float* dl = &BsL[row * BS_STRIDE + c4];
        uint32_t h0, l0, h1, l1, h2, l2, h3, l3;
        split_tf32(v.x, h0, l0); split_tf32(v.y, h1, l1);
        split_tf32(v.z, h2, l2); split_tf32(v.w, h3, l3);
        dh[0] = __uint_as_float(h0); dh[1] = __uint_as_float(h1);
        dh[2] = __uint_as_float(h2); dh[3] = __uint_as_float(h3);
        dl[0] = __uint_as_float(l0); dl[1] = __uint_as_float(l1);
        dl[2] = __uint_as_float(l2); dl[3] = __uint_as_float(l3);
    }
    __syncthreads();

    const int warp = tid >> 5;
    const int lane = tid & 31;
    const int g = lane >> 2;
    const int t = lane & 3;

    const int row0 = (blockIdx.x >> 1) * 256 + warp * 32;

    // row sets: s=0 -> rows row0+g, row0+g+8 ; s=1 -> +16, +24
    int   r[4]  = {row0 + g, row0 + g + 8, row0 + g + 16, row0 + g + 24};
    bool  ok[4];
    const float* pA[4];
#pragma unroll
    for (int q = 0; q < 4; q++) {
        ok[q] = r[q] < N;
        pA[q] = A + (size_t)r[q] * D;
    }

    float acc[2][8][4];
#pragma unroll
    for (int s = 0; s < 2; s++)
#pragma unroll
        for (int j = 0; j < 8; j++)
#pragma unroll
            for (int q = 0; q < 4; q++) acc[s][j][q] = 0.f;

#pragma unroll
    for (int kk = 0; kk < 128; kk += 8) {
        // A fragments for both row sets
        uint32_t ah[2][4], al[2][4];
#pragma unroll
        for (int s = 0; s < 2; s++) {
            float f0 = ok[2*s]   ? __ldg(pA[2*s]   + kk + t)     : 0.f;
            float f1 = ok[2*s+1] ? __ldg(pA[2*s+1] + kk + t)     : 0.f;
            float f2 = ok[2*s]   ? __ldg(pA[2*s]   + kk + t + 4) : 0.f;
            float f3 = ok[2*s+1] ? __ldg(pA[2*s+1] + kk + t + 4) : 0.f;
            split_tf32(f0, ah[s][0], al[s][0]);
            split_tf32(f1, ah[s][1], al[s][1]);
            split_tf32(f2, ah[s][2], al[s][2]);
            split_tf32(f3, ah[s][3], al[s][3]);
        }

        const float* bh0 = &BsH[(kk + t) * BS_STRIDE + g];
        const float* bh1 = &BsH[(kk + t + 4) * BS_STRIDE + g];
        const float* bl0 = &BsL[(kk + t) * BS_STRIDE + g];
        const float* bl1 = &BsL[(kk + t + 4) * BS_STRIDE + g];

#pragma unroll
        for (int j = 0; j < 8; j++) {
            uint32_t b0h = __float_as_uint(bh0[j * 8]);
            uint32_t b1h = __float_as_uint(bh1[j * 8]);
            uint32_t b0l = __float_as_uint(bl0[j * 8]);
            uint32_t b1l = __float_as_uint(bl1[j * 8]);
#pragma unroll
            for (int s = 0; s < 2; s++) {
                mma_tf32(acc[s][j], al[s][0], al[s][1], al[s][2], al[s][3], b0h, b1h);
                mma_tf32(acc[s][j], ah[s][0], ah[s][1], ah[s][2], ah[s][3], b0l, b1l);
                mma_tf32(acc[s][j], ah[s][0], ah[s][1], ah[s][2], ah[s][3], b0h, b1h);
            }
        }
    }

    // epilogue
#pragma unroll
    for (int s = 0; s < 2; s++) {
#pragma unroll
        for (int j = 0; j < 8; j++) {
            float v0 = acc[s][j][0], v1 = acc[s][j][1];
            float v2 = acc[s][j][2], v3 = acc[s][j][3];
            if (RELU) {
                v0 = fmaxf(v0, 0.f); v1 = fmaxf(v1, 0.f);
                v2 = fmaxf(v2, 0.f); v3 = fmaxf(v3, 0.f);
            }
            int c = col_off + j * 8 + 2 * t;
            if (ok[2*s])   *(float2*)(C + (size_t)r[2*s]   * D + c) = make_float2(v0, v1);
            if (ok[2*s+1]) *(float2*)(C + (size_t)r[2*s+1] * D + c) = make_float2(v2, v3);
        }
    }
}

// ---------------------------------------------------------------------------
extern "C" void kernel_launch(void* const* d_in, const int* in_sizes, int n_in,
                              void* d_out, int out_size) {
    const int*   edge_row  = (const int*)d_in[0];
    const int*   edge_col  = (const int*)d_in[1];
    const float* edge_vals = (const float*)d_in[2];
    const float* x         = (const float*)d_in[3];
    const float* sp        = (const float*)d_in[4];
    const float* lw        = (const float*)d_in[5];
    float*       out       = (float*)d_out;

    const int E = in_sizes[0];
    const int N = in_sizes[3] / D;
    const int L = in_sizes[5] / P;

    void *p_ax, *p_hA, *p_hB, *p_ww;
    cudaGetSymbolAddress(&p_ax, g_ax);
    cudaGetSymbolAddress(&p_hA, g_hA);
    cudaGetSymbolAddress(&p_hB, g_hB);
    cudaGetSymbolAddress(&p_ww, g_wwT);

    const int smem_bytes = 2 * 128 * BS_STRIDE * 4;   // 73728
    cudaFuncSetAttribute(gemm_tc<true>,  cudaFuncAttributeMaxDynamicSharedMemorySize, smem_bytes);
    cudaFuncSetAttribute(gemm_tc<false>, cudaFuncAttributeMaxDynamicSharedMemorySize, smem_bytes);

    build_row_ptr_k<<<(N + 256) / 256, 256>>>(edge_row, E, N);
    build_weights_k<<<L * D, D>>>(sp, lw);

    float* bufs[2] = {(float*)p_hA, (float*)p_hB};
    const float* hin = x;
    const int gemm_blocks = 2 * ((N + 255) / 256);
    const int spmm_blocks = (N + 7) / 8;

    for (int l = 0; l < L; l++) {
        spmm_k<<<spmm_blocks, 256>>>(edge_col, edge_vals, hin, N);
        const float* Bm = (const float*)p_ww + (size_t)l * D * D;
        float* Cout = (l == L - 1) ? out : bufs[l & 1];
        if (l < L - 1)
            gemm_tc<true><<<gemm_blocks, 256, smem_bytes>>>((const float*)p_ax, Bm, Cout, N);
        else
            gemm_tc<false><<<gemm_blocks, 256, smem_bytes>>>((const float*)p_ax, Bm, Cout, N);
        hin = Cout;
    }
}